// round 8
// baseline (speedup 1.0000x reference)
#include <cuda_runtime.h>
#include <cstdint>

#define MT 128
#define NT 256
#define K_DIM 8192
#define N_DIM 512
#define CHUNKS (K_DIM / 32)

#define SM_BIAS   0
#define SM_TILES  1024
#define A_OFF     0
#define B_OFF     (MT * 128)                 // 16384
#define STAGE_BYTES ((MT + NT) * 128)        // 49152
#define SMEM_TOTAL (SM_TILES + 4 * STAGE_BYTES)  // 197632

// pre-gathered, tf32-rounded virtual weight [512][8192]
__device__ float g_wfull[(size_t)N_DIM * K_DIM];

// ---------------- helpers ----------------
__device__ __forceinline__ uint32_t smem_u32(const void* p) {
    uint32_t a;
    asm("{ .reg .u64 t; cvta.to.shared.u64 t, %1; cvt.u32.u64 %0, t; }" : "=r"(a) : "l"(p));
    return a;
}
__device__ __forceinline__ uint32_t swz(uint32_t o) { return o ^ ((o >> 3) & 0x70); }

__device__ __forceinline__ void cp16(uint32_t dst, const void* src) {
    asm volatile("cp.async.cg.shared.global [%0], [%1], 16;" :: "r"(dst), "l"(src) : "memory");
}

// swizzled shared read: row = 128B rows, w = 32-bit word index 0..31
__device__ __forceinline__ float lds_sw(const char* base, int row, int w) {
    return *(const float*)(base + row * 128 + (((uint32_t)w ^ (((uint32_t)row & 7u) << 2)) << 2));
}

__device__ __forceinline__ void mma8(float* c, const float* a, const float* b) {
    asm volatile(
        "mma.sync.aligned.m16n8k8.row.col.f32.tf32.tf32.f32 "
        "{%0,%1,%2,%3}, {%4,%5,%6,%7}, {%8,%9}, {%0,%1,%2,%3};"
        : "+f"(c[0]), "+f"(c[1]), "+f"(c[2]), "+f"(c[3])
        : "r"(__float_as_uint(a[0])), "r"(__float_as_uint(a[1])),
          "r"(__float_as_uint(a[2])), "r"(__float_as_uint(a[3])),
          "r"(__float_as_uint(b[0])), "r"(__float_as_uint(b[1])));
}

// ---------------- pre-gather: w_full[n][k] = rna_tf32(weight[n][h(n/32,k/32)*32 + k%32])
__global__ void gather_w(const float* __restrict__ w, const int* __restrict__ rn) {
    const uint32_t r0 = (uint32_t)rn[0], r1 = (uint32_t)rn[1],
                   r2 = (uint32_t)rn[2], r3 = (uint32_t)rn[3];
    int gid = blockIdx.x * 256 + threadIdx.x;     // [0, 512*8192/4)
    int n = gid >> 11;                            // / 2048
    int k = (gid & 2047) << 2;
    uint32_t kb = (uint32_t)(k >> 5), nb = (uint32_t)(n >> 5);
    uint32_t h = ((kb * r0 + nb * r1 + r2) ^ r3) % 32u;
    const float4 v = *(const float4*)(w + n * 1024 + h * 32u + (k & 31));
    uint4 o;
    asm("cvt.rna.tf32.f32 %0, %1;" : "=r"(o.x) : "f"(v.x));
    asm("cvt.rna.tf32.f32 %0, %1;" : "=r"(o.y) : "f"(v.y));
    asm("cvt.rna.tf32.f32 %0, %1;" : "=r"(o.z) : "f"(v.z));
    asm("cvt.rna.tf32.f32 %0, %1;" : "=r"(o.w) : "f"(v.w));
    *(uint4*)(g_wfull + (size_t)n * K_DIM + k) = o;
}

// ---------------- main GEMM ----------------
__global__ void __launch_bounds__(256, 1)
ssl_gemm(const float* __restrict__ x, const float* __restrict__ bias, float* __restrict__ out) {
    extern __shared__ char smem[];
    const uint32_t sb = smem_u32(smem);
    const int tid = threadIdx.x;
    const int lane = tid & 31, wid = tid >> 5;
    const int wm = (wid & 1) * 64;      // warp m offset within CTA tile
    const int wn = (wid >> 1) * 64;     // warp n offset
    const int g = lane >> 2, t = lane & 3;
    const int m0 = blockIdx.y * MT, n0 = blockIdx.x * NT;

    if (tid < 128)
        ((float2*)(smem + SM_BIAS))[tid] = ((const float2*)(bias + n0))[tid];

    float acc[4][8][4];
    #pragma unroll
    for (int i = 0; i < 4; i++)
        #pragma unroll
        for (int j = 0; j < 8; j++)
            #pragma unroll
            for (int q = 0; q < 4; q++) acc[i][j][q] = 0.f;

    const float* aP = x + (size_t)m0 * K_DIM;
    const float* bP = g_wfull + (size_t)n0 * K_DIM;

    // issue cp.async for one 32-wide K chunk into stage (kc & 3)
    auto load_chunk = [&](int kc) {
        const uint32_t base = sb + SM_TILES + (uint32_t)(kc & 3) * STAGE_BYTES;
        const int k0 = kc * 32;
        #pragma unroll
        for (int j = 0; j < 4; j++) {       // A: 128 rows x 8 chunks of 16B
            int i = j * 256 + tid, row = i >> 3, c = i & 7;
            cp16(base + A_OFF + swz((uint32_t)(row * 128 + c * 16)),
                 aP + (size_t)row * K_DIM + k0 + c * 4);
        }
        #pragma unroll
        for (int j = 0; j < 8; j++) {       // B: 256 rows x 8 chunks of 16B
            int i = j * 256 + tid, row = i >> 3, c = i & 7;
            cp16(base + B_OFF + swz((uint32_t)(row * 128 + c * 16)),
                 bP + (size_t)row * K_DIM + k0 + c * 4);
        }
    };

    load_chunk(0); asm volatile("cp.async.commit_group;" ::: "memory");
    load_chunk(1); asm volatile("cp.async.commit_group;" ::: "memory");
    load_chunk(2); asm volatile("cp.async.commit_group;" ::: "memory");

    #pragma unroll 1
    for (int kc = 0; kc < CHUNKS; kc++) {
        __syncthreads();                      // all warps done reading the stage we overwrite
        if (kc + 3 < CHUNKS) load_chunk(kc + 3);
        asm volatile("cp.async.commit_group;" ::: "memory");
        asm volatile("cp.async.wait_group 3;" ::: "memory");
        __syncthreads();

        const char* sA = smem + SM_TILES + (kc & 3) * STAGE_BYTES + A_OFF;
        const char* sB = smem + SM_TILES + (kc & 3) * STAGE_BYTES + B_OFF;
        #pragma unroll
        for (int ks = 0; ks < 4; ks++) {
            const int k0 = ks * 8;
            float af[4][4], bf[8][2];
            #pragma unroll
            for (int mi = 0; mi < 4; mi++) {
                int r = wm + mi * 16 + g;
                af[mi][0] = lds_sw(sA, r,     k0 + t);
                af[mi][1] = lds_sw(sA, r + 8, k0 + t);
                af[mi][2] = lds_sw(sA, r,     k0 + t + 4);
                af[mi][3] = lds_sw(sA, r + 8, k0 + t + 4);
            }
            #pragma unroll
            for (int ni = 0; ni < 8; ni++) {
                int n = wn + ni * 8 + g;
                bf[ni][0] = lds_sw(sB, n, k0 + t);
                bf[ni][1] = lds_sw(sB, n, k0 + t + 4);
            }
            #pragma unroll
            for (int mi = 0; mi < 4; mi++)
                #pragma unroll
                for (int ni = 0; ni < 8; ni++)
                    mma8(acc[mi][ni], af[mi], bf[ni]);
        }
    }

    // epilogue: bias + store
    const float* bs = (const float*)(smem + SM_BIAS);
    #pragma unroll
    for (int mi = 0; mi < 4; mi++) {
        const int r0 = m0 + wm + mi * 16 + g;
        #pragma unroll
        for (int ni = 0; ni < 8; ni++) {
            const int col = wn + ni * 8 + 2 * t;
            float2 v0, v1;
            v0.x = acc[mi][ni][0] + bs[col];
            v0.y = acc[mi][ni][1] + bs[col + 1];
            v1.x = acc[mi][ni][2] + bs[col];
            v1.y = acc[mi][ni][3] + bs[col + 1];
            *(float2*)(out + (size_t)r0 * N_DIM + n0 + col) = v0;
            *(float2*)(out + (size_t)(r0 + 8) * N_DIM + n0 + col) = v1;
        }
    }
}

extern "C" void kernel_launch(void* const* d_in, const int* in_sizes, int n_in,
                              void* d_out, int out_size) {
    (void)in_sizes; (void)n_in; (void)out_size;
    const float* x    = (const float*)d_in[0];
    const float* w    = (const float*)d_in[1];
    const float* bias = (const float*)d_in[2];
    const int*   rn   = (const int*)d_in[3];
    float* out = (float*)d_out;

    gather_w<<<(N_DIM * K_DIM / 4) / 256, 256>>>(w, rn);

    cudaFuncSetAttribute(ssl_gemm, cudaFuncAttributeMaxDynamicSharedMemorySize, SMEM_TOTAL);
    ssl_gemm<<<dim3(N_DIM / NT, 8192 / MT), 256, SMEM_TOTAL>>>(x, bias, out);
}

// round 9
// speedup vs baseline: 1.0023x; 1.0023x over previous
#include <cuda_runtime.h>
#include <cstdint>

#define MT 128
#define NT 256
#define K_DIM 8192
#define N_DIM 512
#define CHUNKS (K_DIM / 32)

#define SM_BIAS   0
#define SM_TILES  1024
#define A_OFF     0
#define B_OFF     (MT * 128)                 // 16384
#define STAGE_BYTES ((MT + NT) * 128)        // 49152
#define SMEM_TOTAL (SM_TILES + 4 * STAGE_BYTES)  // 197632

// pre-gathered, tf32-rounded virtual weight [512][8192]
__device__ float g_wfull[(size_t)N_DIM * K_DIM];

// ---------------- helpers ----------------
__device__ __forceinline__ uint32_t smem_u32(const void* p) {
    uint32_t a;
    asm("{ .reg .u64 t; cvta.to.shared.u64 t, %1; cvt.u32.u64 %0, t; }" : "=r"(a) : "l"(p));
    return a;
}
__device__ __forceinline__ uint32_t swz(uint32_t o) { return o ^ ((o >> 3) & 0x70); }

__device__ __forceinline__ void cp16(uint32_t dst, const void* src) {
    asm volatile("cp.async.cg.shared.global [%0], [%1], 16;" :: "r"(dst), "l"(src) : "memory");
}

// swizzled shared read: row = 128B rows, w = 32-bit word index 0..31
__device__ __forceinline__ float lds_sw(const char* base, int row, int w) {
    return *(const float*)(base + row * 128 + (((uint32_t)w ^ (((uint32_t)row & 7u) << 2)) << 2));
}

__device__ __forceinline__ void mma8(float* c, const float* a, const float* b) {
    asm volatile(
        "mma.sync.aligned.m16n8k8.row.col.f32.tf32.tf32.f32 "
        "{%0,%1,%2,%3}, {%4,%5,%6,%7}, {%8,%9}, {%0,%1,%2,%3};"
        : "+f"(c[0]), "+f"(c[1]), "+f"(c[2]), "+f"(c[3])
        : "r"(__float_as_uint(a[0])), "r"(__float_as_uint(a[1])),
          "r"(__float_as_uint(a[2])), "r"(__float_as_uint(a[3])),
          "r"(__float_as_uint(b[0])), "r"(__float_as_uint(b[1])));
}

// ---------------- pre-gather: w_full[n][k] = rna_tf32(weight[n][h(n/32,k/32)*32 + k%32])
__global__ void gather_w(const float* __restrict__ w, const int* __restrict__ rn) {
    const uint32_t r0 = (uint32_t)rn[0], r1 = (uint32_t)rn[1],
                   r2 = (uint32_t)rn[2], r3 = (uint32_t)rn[3];
    int gid = blockIdx.x * 256 + threadIdx.x;     // [0, 512*8192/4)
    int n = gid >> 11;                            // / 2048
    int k = (gid & 2047) << 2;
    uint32_t kb = (uint32_t)(k >> 5), nb = (uint32_t)(n >> 5);
    uint32_t h = ((kb * r0 + nb * r1 + r2) ^ r3) % 32u;
    const float4 v = *(const float4*)(w + n * 1024 + h * 32u + (k & 31));
    uint4 o;
    asm("cvt.rna.tf32.f32 %0, %1;" : "=r"(o.x) : "f"(v.x));
    asm("cvt.rna.tf32.f32 %0, %1;" : "=r"(o.y) : "f"(v.y));
    asm("cvt.rna.tf32.f32 %0, %1;" : "=r"(o.z) : "f"(v.z));
    asm("cvt.rna.tf32.f32 %0, %1;" : "=r"(o.w) : "f"(v.w));
    *(uint4*)(g_wfull + (size_t)n * K_DIM + k) = o;
}

// ---------------- main GEMM ----------------
__global__ void __launch_bounds__(256, 1)
ssl_gemm(const float* __restrict__ x, const float* __restrict__ bias, float* __restrict__ out) {
    extern __shared__ char smem[];
    const uint32_t sb = smem_u32(smem);
    const int tid = threadIdx.x;
    const int lane = tid & 31, wid = tid >> 5;
    const int wm = (wid & 1) * 64;      // warp m offset within CTA tile
    const int wn = (wid >> 1) * 64;     // warp n offset
    const int g = lane >> 2, t = lane & 3;
    const int m0 = blockIdx.y * MT, n0 = blockIdx.x * NT;

    if (tid < 128)
        ((float2*)(smem + SM_BIAS))[tid] = ((const float2*)(bias + n0))[tid];

    float acc[4][8][4];
    #pragma unroll
    for (int i = 0; i < 4; i++)
        #pragma unroll
        for (int j = 0; j < 8; j++)
            #pragma unroll
            for (int q = 0; q < 4; q++) acc[i][j][q] = 0.f;

    const float* aP = x + (size_t)m0 * K_DIM;
    const float* bP = g_wfull + (size_t)n0 * K_DIM;

    // issue cp.async for one 32-wide K chunk into stage (kc & 3)
    auto load_chunk = [&](int kc) {
        const uint32_t base = sb + SM_TILES + (uint32_t)(kc & 3) * STAGE_BYTES;
        const int k0 = kc * 32;
        #pragma unroll
        for (int j = 0; j < 4; j++) {       // A: 128 rows x 8 chunks of 16B
            int i = j * 256 + tid, row = i >> 3, c = i & 7;
            cp16(base + A_OFF + swz((uint32_t)(row * 128 + c * 16)),
                 aP + (size_t)row * K_DIM + k0 + c * 4);
        }
        #pragma unroll
        for (int j = 0; j < 8; j++) {       // B: 256 rows x 8 chunks of 16B
            int i = j * 256 + tid, row = i >> 3, c = i & 7;
            cp16(base + B_OFF + swz((uint32_t)(row * 128 + c * 16)),
                 bP + (size_t)row * K_DIM + k0 + c * 4);
        }
    };

    load_chunk(0); asm volatile("cp.async.commit_group;" ::: "memory");
    load_chunk(1); asm volatile("cp.async.commit_group;" ::: "memory");
    load_chunk(2); asm volatile("cp.async.commit_group;" ::: "memory");

    #pragma unroll 1
    for (int kc = 0; kc < CHUNKS; kc++) {
        __syncthreads();                      // all warps done reading the stage we overwrite
        if (kc + 3 < CHUNKS) load_chunk(kc + 3);
        asm volatile("cp.async.commit_group;" ::: "memory");
        asm volatile("cp.async.wait_group 3;" ::: "memory");
        __syncthreads();

        const char* sA = smem + SM_TILES + (kc & 3) * STAGE_BYTES + A_OFF;
        const char* sB = smem + SM_TILES + (kc & 3) * STAGE_BYTES + B_OFF;
        #pragma unroll
        for (int ks = 0; ks < 4; ks++) {
            const int k0 = ks * 8;
            float af[4][4], bf[8][2];
            #pragma unroll
            for (int mi = 0; mi < 4; mi++) {
                int r = wm + mi * 16 + g;
                af[mi][0] = lds_sw(sA, r,     k0 + t);
                af[mi][1] = lds_sw(sA, r + 8, k0 + t);
                af[mi][2] = lds_sw(sA, r,     k0 + t + 4);
                af[mi][3] = lds_sw(sA, r + 8, k0 + t + 4);
            }
            #pragma unroll
            for (int ni = 0; ni < 8; ni++) {
                int n = wn + ni * 8 + g;
                bf[ni][0] = lds_sw(sB, n, k0 + t);
                bf[ni][1] = lds_sw(sB, n, k0 + t + 4);
            }
            #pragma unroll
            for (int mi = 0; mi < 4; mi++)
                #pragma unroll
                for (int ni = 0; ni < 8; ni++)
                    mma8(acc[mi][ni], af[mi], bf[ni]);
        }
    }

    // epilogue: bias + store
    const float* bs = (const float*)(smem + SM_BIAS);
    #pragma unroll
    for (int mi = 0; mi < 4; mi++) {
        const int r0 = m0 + wm + mi * 16 + g;
        #pragma unroll
        for (int ni = 0; ni < 8; ni++) {
            const int col = wn + ni * 8 + 2 * t;
            float2 v0, v1;
            v0.x = acc[mi][ni][0] + bs[col];
            v0.y = acc[mi][ni][1] + bs[col + 1];
            v1.x = acc[mi][ni][2] + bs[col];
            v1.y = acc[mi][ni][3] + bs[col + 1];
            *(float2*)(out + (size_t)r0 * N_DIM + n0 + col) = v0;
            *(float2*)(out + (size_t)(r0 + 8) * N_DIM + n0 + col) = v1;
        }
    }
}

extern "C" void kernel_launch(void* const* d_in, const int* in_sizes, int n_in,
                              void* d_out, int out_size) {
    (void)in_sizes; (void)n_in; (void)out_size;
    const float* x    = (const float*)d_in[0];
    const float* w    = (const float*)d_in[1];
    const float* bias = (const float*)d_in[2];
    const int*   rn   = (const int*)d_in[3];
    float* out = (float*)d_out;

    gather_w<<<(N_DIM * K_DIM / 4) / 256, 256>>>(w, rn);

    cudaFuncSetAttribute(ssl_gemm, cudaFuncAttributeMaxDynamicSharedMemorySize, SMEM_TOTAL);
    ssl_gemm<<<dim3(N_DIM / NT, 8192 / MT), 256, SMEM_TOTAL>>>(x, bias, out);
}